// round 10
// baseline (speedup 1.0000x reference)
#include <cuda_runtime.h>
#include <cuda_bf16.h>
#include <math.h>

#define NB 256
#define CC 256
#define TT 64
#define VV 25
#define ROWF (TT*VV)          // 1600 floats per (n,c) row
#define NROWS (NB*CC)         // 65536
#define WARPS_PER_BLK_A 8
#define THREADS_A (WARPS_PER_BLK_A*32)
#define BLOCKS_A (NROWS/WARPS_PER_BLK_A)
#define NSWEEP 7
#define YSTRIDE 12            // 10 floats padded to 48B for float4 loads

__device__ float d_M[256];        // M = W1*W2*W3 (25x10)
__device__ float d_MtM[112];      // M^T M (10x10)
__device__ float d_Y[NROWS * YSTRIDE];   // projected means: 3 MB scratch

// ---------------------------------------------------------------------------
// buildM: M = W1(25x20) W2(20x15) W3(15x10);  MtM = M^T M
// ---------------------------------------------------------------------------
__global__ void buildM_kernel(const float* __restrict__ W1,
                              const float* __restrict__ W2,
                              const float* __restrict__ W3) {
    __shared__ float t1[375];
    __shared__ float Ms[256];
    int tid = threadIdx.x;
    if (tid < 375) {
        int i = tid / 15, j = tid - 15 * i;
        float a = 0.f;
        #pragma unroll
        for (int k = 0; k < 20; k++) a += W1[i * 20 + k] * W2[k * 15 + j];
        t1[tid] = a;
    }
    __syncthreads();
    if (tid < 250) {
        int i = tid / 10, j = tid - 10 * i;
        float a = 0.f;
        #pragma unroll
        for (int k = 0; k < 15; k++) a += t1[i * 15 + k] * W3[k * 10 + j];
        Ms[tid] = a;
        d_M[tid] = a;
    }
    __syncthreads();
    if (tid < 100) {
        int i = tid / 10, j = tid - 10 * i;
        float a = 0.f;
        #pragma unroll
        for (int k = 0; k < 25; k++) a += Ms[k * 10 + i] * Ms[k * 10 + j];
        d_MtM[tid] = a;
    }
}

// ---------------------------------------------------------------------------
// Kernel A: streaming temporal mean + projection. One warp per (n,c) row.
// Lane j<25 sums float4 at phase j over 16 groups (LDG.128, MLP=16, __ldcs),
// warp-shared un-permute folds the 4 t-phases, then lanes 0-9 project
// y = xm . M and write 10 floats (stride 12) to d_Y.
// ---------------------------------------------------------------------------
__global__ __launch_bounds__(THREADS_A)
void mean_project_kernel(const float* __restrict__ x) {
    __shared__ float sh[WARPS_PER_BLK_A][100];
    __shared__ float Ms[250];
    const int tid = threadIdx.x;
    for (int i = tid; i < 250; i += THREADS_A) Ms[i] = d_M[i];
    __syncthreads();

    const int warp = tid >> 5;
    const int lane = tid & 31;
    const size_t r = (size_t)blockIdx.x * WARPS_PER_BLK_A + warp;

    const float4* src = (const float4*)(x + r * ROWF);
    if (lane < 25) {
        float4 acc = make_float4(0.f, 0.f, 0.f, 0.f);
        #pragma unroll
        for (int g = 0; g < 16; g++) {
            float4 v = __ldcs(src + lane + 25 * g);
            acc.x += v.x; acc.y += v.y; acc.z += v.z; acc.w += v.w;
        }
        ((float4*)sh[warp])[lane] = acc;
    }
    __syncwarp();
    if (lane < 25) {
        float mval = (sh[warp][lane] + sh[warp][lane + 25]
                    + sh[warp][lane + 50] + sh[warp][lane + 75]) * (1.f / (float)TT);
        sh[warp][lane] = mval;   // each lane reads only its own 4 slots, writes slot 'lane'
    }
    __syncwarp();
    if (lane < 10) {
        float y = 0.f;
        #pragma unroll
        for (int v = 0; v < 25; v++) y += sh[warp][v] * Ms[v * 10 + lane];
        d_Y[r * YSTRIDE + lane] = y;
    }
}

// ---------------------------------------------------------------------------
// Kernel B: warp-per-n tail. 32 threads, 256 blocks, warp-sync only.
//  G = (Y^T Y - m m^T / C)/(C-1) + 1e-8 M^T M ; Jacobi LogEig ; FC.
// ---------------------------------------------------------------------------
__global__ __launch_bounds__(32)
void tail_kernel(const float* __restrict__ fc_w,
                 const float* __restrict__ fc_b,
                 float* __restrict__ out) {
    const int lane = threadIdx.x;
    const int n = blockIdx.x;

    // ---- accumulate Y^T Y and column sums over 8 rows per lane ------------
    float m[10];
    float S[55];
    #pragma unroll
    for (int l = 0; l < 10; l++) m[l] = 0.f;
    #pragma unroll
    for (int e = 0; e < 55; e++) S[e] = 0.f;

    const float4* Yb = (const float4*)(d_Y + (size_t)n * CC * YSTRIDE);
    #pragma unroll
    for (int rr = 0; rr < 8; rr++) {
        const int c = lane + rr * 32;
        const float4* rp = Yb + c * 3;           // 48B-aligned rows
        float4 a0 = rp[0], a1 = rp[1], a2 = rp[2];
        float y[10] = {a0.x, a0.y, a0.z, a0.w, a1.x, a1.y, a1.z, a1.w, a2.x, a2.y};
        #pragma unroll
        for (int l = 0; l < 10; l++) m[l] += y[l];
        int idx = 0;
        #pragma unroll
        for (int i = 0; i < 10; i++)
            #pragma unroll
            for (int j = i; j < 10; j++) { S[idx] += y[i] * y[j]; idx++; }
    }
    // ---- warp butterfly reduce (all lanes end with totals) ----------------
    #pragma unroll
    for (int o = 16; o > 0; o >>= 1) {
        #pragma unroll
        for (int l = 0; l < 10; l++) m[l] += __shfl_xor_sync(0xffffffffu, m[l], o);
        #pragma unroll
        for (int e = 0; e < 55; e++) S[e] += __shfl_xor_sync(0xffffffffu, S[e], o);
    }

    __shared__ float As[100], Us[100], Lw[10], Lm[100];
    if (lane == 0) {
        int idx = 0;
        #pragma unroll
        for (int i = 0; i < 10; i++)
            #pragma unroll
            for (int j = i; j < 10; j++) {
                float g = (S[idx] - m[i] * m[j] * (1.f / (float)CC)) * (1.f / (float)(CC - 1))
                        + 1e-8f * d_MtM[i * 10 + j];
                As[i * 10 + j] = g;
                As[j * 10 + i] = g;
                idx++;
            }
    }
    #pragma unroll
    for (int e = lane; e < 100; e += 32) Us[e] = ((e / 10) == (e % 10)) ? 1.f : 0.f;
    __syncwarp();

    // ---- Jacobi eigensolver: 5 disjoint pairs/round, warp-sync only -------
    const bool act = (lane < 25);
    for (int sweep = 0; sweep < NSWEEP; sweep++) {
        for (int r = 0; r < 9; r++) {
            int p_[2], q_[2], k_[2];
            float c_[2], s_[2], akp[2], akq[2], ukp[2], ukq[2];
            if (act) {
                #pragma unroll
                for (int t = 0; t < 2; t++) {
                    int item = lane + 25 * t;
                    int pj = item / 10, k = item - 10 * pj;
                    int a1 = (pj == 0) ? 0 : ((pj - 1 + r) % 9) + 1;
                    int a2 = ((8 - pj + r) % 9) + 1;
                    int p = min(a1, a2), q = max(a1, a2);
                    float apq = As[p * 10 + q];
                    float app = As[p * 10 + p];
                    float aqq = As[q * 10 + q];
                    float cc = 1.f, ss = 0.f;
                    if (fabsf(apq) > 1e-20f) {
                        float tau = (aqq - app) / (2.f * apq);
                        float tt = 1.f / (fabsf(tau) + sqrtf(1.f + tau * tau));
                        if (tau < 0.f) tt = -tt;
                        cc = rsqrtf(1.f + tt * tt);
                        ss = tt * cc;
                    }
                    p_[t] = p; q_[t] = q; k_[t] = k; c_[t] = cc; s_[t] = ss;
                    akp[t] = As[k * 10 + p]; akq[t] = As[k * 10 + q];
                    ukp[t] = Us[k * 10 + p]; ukq[t] = Us[k * 10 + q];
                }
            }
            __syncwarp();
            if (act) {
                #pragma unroll
                for (int t = 0; t < 2; t++) {
                    As[k_[t] * 10 + p_[t]] = c_[t] * akp[t] - s_[t] * akq[t];
                    As[k_[t] * 10 + q_[t]] = s_[t] * akp[t] + c_[t] * akq[t];
                    Us[k_[t] * 10 + p_[t]] = c_[t] * ukp[t] - s_[t] * ukq[t];
                    Us[k_[t] * 10 + q_[t]] = s_[t] * ukp[t] + c_[t] * ukq[t];
                }
            }
            __syncwarp();
            if (act) {
                #pragma unroll
                for (int t = 0; t < 2; t++) {
                    float apk = As[p_[t] * 10 + k_[t]];
                    float aqk = As[q_[t] * 10 + k_[t]];
                    As[p_[t] * 10 + k_[t]] = c_[t] * apk - s_[t] * aqk;
                    As[q_[t] * 10 + k_[t]] = s_[t] * apk + c_[t] * aqk;
                }
            }
            __syncwarp();
        }
    }

    // ---- LogEig reconstruct ----------------------------------------------
    if (lane < 10) Lw[lane] = logf(fmaxf(As[lane * 10 + lane], 1e-30f));
    __syncwarp();
    #pragma unroll
    for (int e = lane; e < 100; e += 32) {
        int i = e / 10, j = e - 10 * i;
        float a = 0.f;
        #pragma unroll
        for (int l = 0; l < 10; l++) a += Us[i * 10 + l] * Lw[l] * Us[j * 10 + l];
        Lm[e] = a;
    }
    __syncwarp();

    // ---- FC ----------------------------------------------------------------
    #pragma unroll
    for (int o = lane; o < 64; o += 32) {
        float a = fc_b[o];
        const float* wr = fc_w + o * 100;
        #pragma unroll
        for (int f = 0; f < 100; f++) a += Lm[f] * __ldg(&wr[f]);
        out[(size_t)n * 64 + o] = a;
    }
}

extern "C" void kernel_launch(void* const* d_in, const int* in_sizes, int n_in,
                              void* d_out, int out_size) {
    const float* x    = (const float*)d_in[0];
    const float* W1   = (const float*)d_in[1];
    const float* W2   = (const float*)d_in[2];
    const float* W3   = (const float*)d_in[3];
    const float* fc_w = (const float*)d_in[4];
    const float* fc_b = (const float*)d_in[5];
    float* out = (float*)d_out;

    buildM_kernel<<<1, 512>>>(W1, W2, W3);
    mean_project_kernel<<<BLOCKS_A, THREADS_A>>>(x);
    tail_kernel<<<NB, 32>>>(fc_w, fc_b, out);
}